// round 17
// baseline (speedup 1.0000x reference)
#include <cuda_runtime.h>
#include <math.h>

#define BB 8
#define DD 256
#define NL 10000
#define KN 32
#define KC 10032
#define NS 100

#define HISTB (NS * BB)                 // 800 histogram CTAs
#define ROWS_PER_CTA 64
#define SCAN_PER_B ((NL + ROWS_PER_CTA - 1) / ROWS_PER_CTA)   // 157
#define SCANB (BB * SCAN_PER_B)         // 1256
#define TOTB (HISTB + SCANB + 1)        // +1 new-logit writer CTA
#define FLAG_THR (-100.0f)
#define SDIM4 12                        // partial-scan float4s per row (48 dims)
#define SGRP 8                          // samples per k_boot CTA
#define NGRP ((NS + 1 + SGRP - 1) / SGRP)   // 13

// scratch (no allocations allowed)
__device__ float g_logits[BB * KC];            // UB for unflagged live, exact for flagged/new
__device__ float g_boot[NS * BB * DD];         // [n][b*DD+d]  (coalesced both sides)
__device__ int   g_cnt[NS * BB * 32];          // per-sample new-particle counts
__device__ unsigned g_MliveU[BB];              // encoded max flagged live logit (0 = none; reset by reducer)
__device__ int   g_bcnt[BB];                   // per-b boot-CTA tickets (reset by reducer)

__device__ __forceinline__ unsigned fenc(float f) {
    unsigned u = __float_as_uint(f);
    return (u & 0x80000000u) ? ~u : (u | 0x80000000u);
}
__device__ __forceinline__ float fdec(unsigned u) {
    return (u & 0x80000000u) ? __uint_as_float(u & 0x7FFFFFFFu) : __uint_as_float(~u);
}

__device__ __forceinline__ float dsq(float4 a, float4 c) {
    float d0 = a.x - c.x, d1 = a.y - c.y, d2 = a.z - c.z, d3 = a.w - c.w;
    return d0 * d0 + d1 * d1 + d2 * d2 + d3 * d3;
}

__device__ __forceinline__ float blockMax256(float v, float* red) {
#pragma unroll
    for (int o = 16; o; o >>= 1) v = fmaxf(v, __shfl_xor_sync(0xffffffffu, v, o));
    int wid = threadIdx.x >> 5;
    if ((threadIdx.x & 31) == 0) red[wid] = v;
    __syncthreads();
    if (threadIdx.x < 32) {
        float x = (threadIdx.x < 8) ? red[threadIdx.x] : -INFINITY;
#pragma unroll
        for (int o = 4; o; o >>= 1) x = fmaxf(x, __shfl_xor_sync(0xffffffffu, x, o));
        if (threadIdx.x == 0) red[0] = x;
    }
    __syncthreads();
    v = red[0];
    __syncthreads();
    return v;
}

__device__ __forceinline__ float blockSum256(float v, float* red) {
#pragma unroll
    for (int o = 16; o; o >>= 1) v += __shfl_xor_sync(0xffffffffu, v, o);
    int wid = threadIdx.x >> 5;
    if ((threadIdx.x & 31) == 0) red[wid] = v;
    __syncthreads();
    if (threadIdx.x < 32) {
        float x = (threadIdx.x < 8) ? red[threadIdx.x] : 0.f;
#pragma unroll
        for (int o = 4; o; o >>= 1) x += __shfl_xor_sync(0xffffffffu, x, o);
        if (threadIdx.x == 0) red[0] = x;
    }
    __syncthreads();
    v = red[0];
    __syncthreads();
    return v;
}

// ---------- kernel 1: idx histogram + 48-dim partial scan + inline exact resolve ----------
__global__ void k_scan(const float* __restrict__ xt,
                       const float* __restrict__ live_x0,
                       const float* __restrict__ live_ll,
                       const float* __restrict__ ll,
                       const float* __restrict__ tsp,
                       const int* __restrict__ bidx) {
    __shared__ int cnt32[32];
    __shared__ int fl_rows[ROWS_PER_CTA];
    __shared__ int fl_n;
    int bid = blockIdx.x, t = threadIdx.x;

    if (bid < HISTB) {
        // histogram of idx over the new-particle range [NL, KC)
        int n = bid >> 3, b = bid & 7;
        if (t < 32) cnt32[t] = 0;
        __syncthreads();
        const uint4* src = (const uint4*)(bidx + ((size_t)n * BB + b) * KC);
        for (int i = t; i < KC / 4; i += 256) {
            uint4 v = src[i];
            int s0 = (int)v.x - NL, s1 = (int)v.y - NL;
            int s2 = (int)v.z - NL, s3 = (int)v.w - NL;
            if (s0 >= 0) atomicAdd(&cnt32[s0], 1);
            if (s1 >= 0) atomicAdd(&cnt32[s1], 1);
            if (s2 >= 0) atomicAdd(&cnt32[s2], 1);
            if (s3 >= 0) atomicAdd(&cnt32[s3], 1);
        }
        __syncthreads();
        if (t < 32) g_cnt[((size_t)n * BB + b) * 32 + t] = cnt32[t];
        return;
    }
    if (bid == HISTB + SCANB) {
        // new-particle logits: exactly ll (gaussian correction cancels)
        int b = t >> 5, j = t & 31;
        g_logits[(size_t)b * KC + NL + j] = ll[b * KN + j];
        return;
    }

    // partial scan: first 48 dims of each live row -> upper bound on its logit.
    int s = bid - HISTB;
    int b = s / SCAN_PER_B;
    int r0 = (s - b * SCAN_PER_B) * ROWS_PER_CTA;
    int w = t >> 5, lane = t & 31;
    int half = lane >> 4, sl = lane & 15;
    bool act = sl < SDIM4;

    if (t == 0) fl_n = 0;
    __syncthreads();

    float ts = *tsp;
    float inv2 = 0.5f / (ts * ts), lg = logf(ts);
    const float4* xtr = (const float4*)(xt + (size_t)b * DD);
    float4 zf = make_float4(0.f, 0.f, 0.f, 0.f);
    float4 c = act ? xtr[sl] : zf;  // first 48 floats of xt

    int rbase = r0 + w * 8 + half;  // rows rbase, rbase+2, rbase+4, rbase+6
    const float4* lx = (const float4*)(live_x0 + (size_t)b * NL * DD);

    int row0 = rbase, row1 = rbase + 2, row2 = rbase + 4, row3 = rbase + 6;
    bool v0 = act && row0 < NL, v1 = act && row1 < NL;
    bool v2 = act && row2 < NL, v3 = act && row3 < NL;
    float4 a0 = v0 ? lx[(size_t)row0 * (DD / 4) + sl] : c;
    float4 a1 = v1 ? lx[(size_t)row1 * (DD / 4) + sl] : c;
    float4 a2 = v2 ? lx[(size_t)row2 * (DD / 4) + sl] : c;
    float4 a3 = v3 ? lx[(size_t)row3 * (DD / 4) + sl] : c;
    float q0 = dsq(a0, c), q1 = dsq(a1, c), q2 = dsq(a2, c), q3 = dsq(a3, c);
#pragma unroll
    for (int o = 8; o; o >>= 1) {  // reduce within 16-lane half-warp
        q0 += __shfl_xor_sync(0xffffffffu, q0, o);
        q1 += __shfl_xor_sync(0xffffffffu, q1, o);
        q2 += __shfl_xor_sync(0xffffffffu, q2, o);
        q3 += __shfl_xor_sync(0xffffffffu, q3, o);
    }
    if (sl == 0) {
        const float* lr = live_ll + (size_t)b * NL;
        float* Lb = g_logits + (size_t)b * KC;
        float qs[4] = {q0, q1, q2, q3};
#pragma unroll
        for (int j = 0; j < 4; j++) {
            int row = rbase + 2 * j;
            if (row < NL) {
                float ub = lr[row] - qs[j] * inv2 - lg;   // upper bound (partial distance >= 0)
                Lb[row] = ub;
                if (ub > FLAG_THR) {
                    int pos = atomicAdd(&fl_n, 1);
                    fl_rows[pos] = row;   // <= 64 rows per CTA by construction
                }
            }
        }
    }
    __syncthreads();

    // inline exact resolve for flagged rows (rare): full 256-dim distance, warp per row
    int nf = fl_n;
    if (nf > 0) {
        float4 c0 = xtr[lane], c1 = xtr[lane + 32];
        for (int i = w; i < nf; i += 8) {
            int row = fl_rows[i];
            const float4* r = (const float4*)(live_x0 + ((size_t)b * NL + row) * DD);
            float4 e0 = r[lane], e1 = r[lane + 32];
            float sfull = dsq(e0, c0) + dsq(e1, c1);
#pragma unroll
            for (int o = 16; o; o >>= 1) sfull += __shfl_xor_sync(0xffffffffu, sfull, o);
            if (lane == 0) {
                float l = live_ll[(size_t)b * NL + row] - sfull * inv2 - lg;
                g_logits[(size_t)b * KC + row] = l;   // overwrite UB with exact
                atomicMax(&g_MliveU[b], fenc(l));
            }
        }
    }
}

// ---------- kernel 2: bootstrap + score + fused per-b std/flag (grid = [NGRP, BB]) ----------
__global__ void k_boot(const float* __restrict__ xt,
                       const float* __restrict__ live_x0,
                       const float* __restrict__ x0,
                       const float* __restrict__ ll,
                       const int* __restrict__ bidx,
                       const float* __restrict__ tsp,
                       float* __restrict__ out, int out_size) {
    __shared__ float wsm[KN][SGRP];      // weights [row j][sample s]
    __shared__ float zvec[SGRP];
    __shared__ int   fastv[SGRP];        // 0=slow, 1=fast, 2=invalid
    __shared__ float red[8];
    __shared__ int   sh_tick;
    int g = blockIdx.x, b = blockIdx.y, t = threadIdx.x;
    int w = t >> 5, lane = t & 31;
    int n0 = g * SGRP;
    float ts = *tsp;

    // warp w computes weights for sample n0+w
    {
        int n = n0 + w;
        if (n <= NS) {
            int c = (n == NS) ? 1 : g_cnt[((size_t)n * BB + b) * 32 + lane];
            float lv = ll[b * KN + lane];
            float m = (c > 0) ? lv : -INFINITY;
#pragma unroll
            for (int o = 16; o; o >>= 1) m = fmaxf(m, __shfl_xor_sync(0xffffffffu, m, o));
            float wt = (c > 0) ? (float)c * expf(lv - m) : 0.f;
            float z = wt;
#pragma unroll
            for (int o = 16; o; o >>= 1) z += __shfl_xor_sync(0xffffffffu, z, o);
            wsm[lane][w] = wt;
            if (lane == 0) {
                zvec[w] = z;
                unsigned mu = g_MliveU[b];
                float Mlive = mu ? fdec(mu) : -INFINITY;
                Mlive = fmaxf(Mlive, FLAG_THR);
                fastv[w] = ((m > -INFINITY) && (Mlive <= m - 90.f)) ? 1 : 0;
            }
        } else if (lane == 0) {
            fastv[w] = 2;
        }
    }
    __syncthreads();

    float xtv = xt[(size_t)b * DD + t];
    float acc[SGRP];
#pragma unroll
    for (int s = 0; s < SGRP; s++) acc[s] = 0.f;

    // fused weighted sum: row j once from global (L2-warm), 8 FMA into 8 accumulators
    const float* xb = x0 + (size_t)b * KN * DD + t;
#pragma unroll 4
    for (int j = 0; j < KN; j++) {
        float xj = xb[j * DD];
        const float4* wp = (const float4*)&wsm[j][0];
        float4 w0 = wp[0], w1 = wp[1];
        acc[0] = fmaf(w0.x, xj, acc[0]); acc[1] = fmaf(w0.y, xj, acc[1]);
        acc[2] = fmaf(w0.z, xj, acc[2]); acc[3] = fmaf(w0.w, xj, acc[3]);
        acc[4] = fmaf(w1.x, xj, acc[4]); acc[5] = fmaf(w1.y, xj, acc[5]);
        acc[6] = fmaf(w1.z, xj, acc[6]); acc[7] = fmaf(w1.w, xj, acc[7]);
    }

#pragma unroll
    for (int s = 0; s < SGRP; s++) {
        int n = n0 + s;
        if (fastv[s] == 1) {
            float val = acc[s] / (zvec[s] * ts) - xtv / ts;
            if (n == NS) out[(size_t)b * DD + t] = val;
            else         g_boot[(size_t)n * (BB * DD) + b * DD + t] = val;
        }
    }

    // exact slow path for any non-fast sample (never taken with this data)
    for (int s = 0; s < SGRP; s++) {
        if (fastv[s] != 0) continue;
        int n = n0 + s;
        bool is_score = (n == NS);
        const int* idx = bidx + ((size_t)n * BB + b) * KC;
        const float* L = g_logits + (size_t)b * KC;
        float mm = -INFINITY;
        if (is_score) { for (int k = t; k < KC; k += 256) mm = fmaxf(mm, L[k]); }
        else          { for (int i = t; i < KC; i += 256) mm = fmaxf(mm, L[idx[i]]); }
        mm = blockMax256(mm, red);
        float zz = 0.f;
        if (is_score) { for (int k = t; k < KC; k += 256) zz += expf(L[k] - mm); }
        else          { for (int i = t; i < KC; i += 256) zz += expf(L[idx[i]] - mm); }
        float z = blockSum256(zz, red);
        float a = 0.f;
        for (int i = 0; i < KC; i++) {
            int k = is_score ? i : idx[i];
            float wv = expf(L[k] - mm);
            if (wv != 0.f) {
                const float* r = (k < NL) ? live_x0 + ((size_t)b * NL + k) * DD
                                          : x0 + ((size_t)b * KN + (k - NL)) * DD;
                a = fmaf(wv, r[t], a);
            }
        }
        float val = a / (z * ts) - xtv / ts;
        if (is_score) out[(size_t)b * DD + t] = val;
        else          g_boot[(size_t)n * (BB * DD) + b * DD + t] = val;
    }

    // ---- per-b ticket: last CTA reduces this b's std + emits flag + resets state ----
    __threadfence();
    __syncthreads();
    if (t == 0) sh_tick = atomicAdd(&g_bcnt[b], 1);
    __syncthreads();
    if (sh_tick == NGRP - 1) {
        const float* p = g_boot + (size_t)b * DD + t;
        float x[NS];
#pragma unroll
        for (int i = 0; i < NS; i++) x[i] = p[(size_t)i * (BB * DD)];
        float sm = 0.f;
#pragma unroll
        for (int i = 0; i < NS; i++) sm += x[i];
        float mean = sm * (1.f / NS);
        float q = 0.f;
#pragma unroll
        for (int i = 0; i < NS; i++) { float dv = x[i] - mean; q = fmaf(dv, dv, q); }
        float sigma = sqrtf(q * (1.f / (NS - 1)));
        int ok = sigma < 0.1f * ts;
        int all = __syncthreads_and(ok);
        if (t == 0) {
            if (out_size >= BB * DD + BB) out[BB * DD + b] = all ? 1.f : 0.f;
            g_bcnt[b] = 0;      // reset for next graph replay
            g_MliveU[b] = 0u;
        }
    }
}

extern "C" void kernel_launch(void* const* d_in, const int* in_sizes, int n_in,
                              void* d_out, int out_size) {
    const float* xt      = (const float*)d_in[0];
    const float* live_x0 = (const float*)d_in[1];
    const float* live_ll = (const float*)d_in[2];
    const float* x0      = (const float*)d_in[3];
    const float* ll      = (const float*)d_in[4];
    const float* tsp     = (const float*)d_in[5];
    const int*   bidx    = (const int*)d_in[6];
    float* out = (float*)d_out;

    k_scan<<<TOTB, 256>>>(xt, live_x0, live_ll, ll, tsp, bidx);

    dim3 g2(NGRP, BB);
    k_boot<<<g2, 256>>>(xt, live_x0, x0, ll, bidx, tsp, out, out_size);
}